// round 16
// baseline (speedup 1.0000x reference)
#include <cuda_runtime.h>
#include <cuda_bf16.h>
#include <cstdint>

// ---------------------------------------------------------------------------
// GlobalIntrinsicLinear: y = x @ (W0 + Fastfood(theta))^T + b
// Pass-1 FWHT collapsed analytically; row FWHT done warp-level (shfl, no
// block barriers); pass-2 = two register stride-32 passes, 2nd fused into
// the W split (writes g_B directly).
// GEMM (R12 proven config): bf16 3-term split with A-fragment sharing
// (12 super tiles Xhi*(Whi,Wlo) + 12 normal tiles Xlo*Whi), CTA 128x128,
// 8 warps, 2-stage double buffer, 2 CTAs/SM.
// R15: fix the broken g_scale reduction from R14 (illegal shfl width 64).
// ---------------------------------------------------------------------------

#define LL   (1 << 20)
#define DD   (1024 * 768)
#define OUTF 1024
#define INF  768
#define MTOT 16384
#define KA   1536          // 2 * 768 storage K
#define NIT  24            // 12 super + 12 normal tiles

#define BM 128
#define BN 128
#define RSB 144            // smem row stride bytes (128B data + 16B pad)
#define OP_BYTES (128 * RSB)       // 18432 per operand tile
#define STAGE   (3 * OP_BYTES)     // A + B0 + B1 = 55296
#define NSTAGE  2

// Scratch (device globals; no cudaMalloc allowed)
__device__ float g_a[1024];
__device__ float g_b[1024];
__device__ float g_u[LL];
__device__ float g_part[128];
__device__ float g_scale;
__device__ __align__(16) __nv_bfloat16 g_A[(size_t)MTOT * KA];   // 50.3 MB
__device__ __align__(16) __nv_bfloat16 g_B[(size_t)OUTF * KA];   // 3 MB

// ======================= PTX helpers =======================================
__device__ __forceinline__ uint32_t smem_u32(const void* p) {
    uint32_t a;
    asm("{ .reg .u64 t; cvta.to.shared.u64 t, %1; cvt.u32.u64 %0, t; }" : "=r"(a) : "l"(p));
    return a;
}

__device__ __forceinline__ void cp_async16(uint32_t dst, const void* src) {
    asm volatile("cp.async.cg.shared.global [%0], [%1], 16;" :: "r"(dst), "l"(src));
}
#define CP_COMMIT() asm volatile("cp.async.commit_group;" ::: "memory")
template <int N>
__device__ __forceinline__ void cp_wait() {
    asm volatile("cp.async.wait_group %0;" :: "n"(N) : "memory");
}

__device__ __forceinline__ void ldmat_x4(uint32_t& r0, uint32_t& r1, uint32_t& r2,
                                         uint32_t& r3, uint32_t addr) {
    asm volatile("ldmatrix.sync.aligned.m8n8.x4.shared.b16 {%0,%1,%2,%3}, [%4];"
                 : "=r"(r0), "=r"(r1), "=r"(r2), "=r"(r3) : "r"(addr));
}

__device__ __forceinline__ void mma16816(float* d, const uint32_t* a,
                                         uint32_t b0, uint32_t b1) {
    asm volatile(
        "mma.sync.aligned.m16n8k16.row.col.f32.bf16.bf16.f32 "
        "{%0,%1,%2,%3}, {%4,%5,%6,%7}, {%8,%9}, {%0,%1,%2,%3};"
        : "+f"(d[0]), "+f"(d[1]), "+f"(d[2]), "+f"(d[3])
        : "r"(a[0]), "r"(a[1]), "r"(a[2]), "r"(a[3]), "r"(b0), "r"(b1));
}

// ======================= warp-level FWHT ===================================
// Lane l holds elements e = j*32 + l (j = register index 0..31).
// Bits 5-9: in-register butterflies. Bits 0-4: shfl_xor across lanes.
__device__ __forceinline__ void fwht32_reg(float* r) {
#pragma unroll
    for (int h = 1; h < 32; h <<= 1) {
#pragma unroll
        for (int i = 0; i < 32; i++) {
            if ((i & h) == 0) {
                float a = r[i], b = r[i | h];
                r[i] = a + b;
                r[i | h] = a - b;
            }
        }
    }
}

__device__ __forceinline__ void fwht1024_warp(float* r, int lane) {
    fwht32_reg(r);                        // bits 5..9
#pragma unroll
    for (int h = 1; h < 32; h <<= 1) {    // bits 0..4 across lanes
        bool upper = (lane & h) != 0;
#pragma unroll
        for (int j = 0; j < 32; j++) {
            float v = __shfl_xor_sync(0xFFFFFFFFu, r[j], h);
            r[j] = upper ? (v - r[j]) : (r[j] + v);
        }
    }
}

// ======================= Fastfood kernels ==================================
// One block, 2 warps: warp w computes FWHT1024(BB[w*1024:]*theta[w*1024:])
__global__ void k_ab(const float* __restrict__ theta, const float* __restrict__ BB,
                     int ntheta) {
    int wid = threadIdx.x >> 5;
    int lane = threadIdx.x & 31;
    int gbase = wid * 1024;
    float r[32];
#pragma unroll
    for (int j = 0; j < 32; j++) {
        int gi = gbase + j * 32 + lane;
        float t = (gi < ntheta) ? theta[gi] : 0.0f;
        r[j] = BB[gi] * t;
    }
    fwht1024_warp(r, lane);
    float* dst = (wid == 0) ? g_a : g_b;
#pragma unroll
    for (int j = 0; j < 32; j++) dst[j * 32 + lane] = r[j];
}

// Warp-per-row fused gather + GG mult + row FWHT + GG^2 partials.
// 128 blocks x 8 warps = 1024 rows. One barrier per block (reduction only).
__global__ void k_gather_rows(const int* __restrict__ Pi, const float* __restrict__ GG) {
    __shared__ float wsum[8];
    const int wid = threadIdx.x >> 5;
    const int lane = threadIdx.x & 31;
    const int row = blockIdx.x * 8 + wid;
    const int base = row * 1024;

    float r[32];
    float gsum = 0.0f;
#pragma unroll
    for (int j = 0; j < 32; j++) {
        int e = base + j * 32 + lane;
        int idx = Pi[e] & (LL - 1);
        int c = idx & 1023;
        float v = g_a[c] + (((idx >> 10) & 1) ? -g_b[c] : g_b[c]);
        float g = GG[e];
        gsum += g * g;
        r[j] = v * g;
    }
    fwht1024_warp(r, lane);
#pragma unroll
    for (int j = 0; j < 32; j++) g_u[base + j * 32 + lane] = r[j];

#pragma unroll
    for (int h = 16; h > 0; h >>= 1) gsum += __shfl_xor_sync(0xFFFFFFFFu, gsum, h);
    if (lane == 0) wsum[wid] = gsum;
    __syncthreads();
    if (threadIdx.x == 0) {
        float s = 0.0f;
#pragma unroll
        for (int w = 0; w < 8; w++) s += wsum[w];
        g_part[blockIdx.x] = s;
    }
}

// Column FWHT pass over bits 10..14 (element stride 1024).
// Block 0 additionally folds the 128-entry GG^2 reduction into g_scale.
__global__ void k_fwht_colA(float* __restrict__ v) {
    if (blockIdx.x == 0 && threadIdx.x < 32) {
        float s = g_part[threadIdx.x] + g_part[threadIdx.x + 32] +
                  g_part[threadIdx.x + 64] + g_part[threadIdx.x + 96];
#pragma unroll
        for (int h = 16; h > 0; h >>= 1) s += __shfl_xor_sync(0xFFFFFFFFu, s, h);
        if (threadIdx.x == 0) g_scale = 1.0f / sqrtf(s * (float)DD);
    }
    int low = (blockIdx.x & 3) * 256 + threadIdx.x;
    int hi = blockIdx.x >> 2;
    size_t base = (size_t)hi * 32768 + low;
    float r[32];
#pragma unroll
    for (int m = 0; m < 32; m++) r[m] = v[base + (size_t)m * 1024];
    fwht32_reg(r);
#pragma unroll
    for (int m = 0; m < 32; m++) v[base + (size_t)m * 1024] = r[m];
}

__device__ __forceinline__ uint32_t pack_bf16x2(float x, float y) {
    __nv_bfloat162 h(__float2bfloat16(x), __float2bfloat16(y));
    return *(uint32_t*)&h;
}

// Column FWHT pass over bits 15..19 (stride 32768) fused with weight build:
// i = base + m*32768; i < DD <=> m < 24; writes split-bf16 g_B directly.
__global__ void k_fwht_colB_buildB(const float* __restrict__ v,
                                   const float* __restrict__ W0) {
    int low = (blockIdx.x & 3) * 256 + threadIdx.x;
    int r2 = blockIdx.x >> 2;
    size_t base = (size_t)r2 * 1024 + low;
    float r[32];
#pragma unroll
    for (int m = 0; m < 32; m++) r[m] = v[base + (size_t)m * 32768];
    fwht32_reg(r);
    const float sc = g_scale;
#pragma unroll
    for (int m = 0; m < 24; m++) {
        size_t i = base + (size_t)m * 32768;
        int n = (int)(i / 768);
        int k = (int)(i - (size_t)n * 768);
        float w = W0[i] + r[m] * sc;
        __nv_bfloat16 hi = __float2bfloat16(w);
        __nv_bfloat16 lo = __float2bfloat16(w - __bfloat162float(hi));
        size_t bb = (size_t)n * KA + k;
        g_B[bb] = hi;
        g_B[bb + INF] = lo;
    }
}

// ======================= Operand prep ======================================
__device__ __forceinline__ void split8(const float4 v0, const float4 v1,
                                       uint4& hi, uint4& lo) {
    float h0 = __bfloat162float(__float2bfloat16(v0.x));
    float h1 = __bfloat162float(__float2bfloat16(v0.y));
    float h2 = __bfloat162float(__float2bfloat16(v0.z));
    float h3 = __bfloat162float(__float2bfloat16(v0.w));
    float h4 = __bfloat162float(__float2bfloat16(v1.x));
    float h5 = __bfloat162float(__float2bfloat16(v1.y));
    float h6 = __bfloat162float(__float2bfloat16(v1.z));
    float h7 = __bfloat162float(__float2bfloat16(v1.w));
    hi.x = pack_bf16x2(v0.x, v0.y);
    hi.y = pack_bf16x2(v0.z, v0.w);
    hi.z = pack_bf16x2(v1.x, v1.y);
    hi.w = pack_bf16x2(v1.z, v1.w);
    lo.x = pack_bf16x2(v0.x - h0, v0.y - h1);
    lo.y = pack_bf16x2(v0.z - h2, v0.w - h3);
    lo.z = pack_bf16x2(v1.x - h4, v1.y - h5);
    lo.w = pack_bf16x2(v1.z - h6, v1.w - h7);
}

// A' = [Xhi | Xlo]
__global__ void k_split_x(const float* __restrict__ X) {
    int i8 = blockIdx.x * blockDim.x + threadIdx.x;
    if (i8 < MTOT * INF / 8) {
        int m = i8 / (INF / 8);
        int k = (i8 - m * (INF / 8)) * 8;
        const float* xp = X + (size_t)m * INF + k;
        float4 v0 = *(const float4*)(xp);
        float4 v1 = *(const float4*)(xp + 4);
        uint4 hi, lo;
        split8(v0, v1, hi, lo);
        size_t base = (size_t)m * KA + k;
        *(uint4*)(g_A + base) = hi;
        *(uint4*)(g_A + base + INF) = lo;
    }
}

// ======================= mma.sync GEMM (R12 proven config) =================
__device__ __forceinline__ void load_stage(uint32_t sb, const __nv_bfloat16* gA,
                                           const __nv_bfloat16* gB, int t, int tid) {
    const int s = (t < 12) ? t : t - 12;
    const int a_k = (t < 12) ? s * 64 : 768 + s * 64;
    const int b0_k = s * 64;
#pragma unroll
    for (int j = 0; j < 4; j++) {
        int ca = tid + j * 256;
        int r = ca >> 3, c = ca & 7;
        cp_async16(sb + r * RSB + c * 16, gA + (size_t)r * KA + a_k + c * 8);
    }
#pragma unroll
    for (int j = 0; j < 4; j++) {
        int ca = tid + j * 256;
        int r = ca >> 3, c = ca & 7;
        cp_async16(sb + OP_BYTES + r * RSB + c * 16, gB + (size_t)r * KA + b0_k + c * 8);
    }
    if (t < 12) {
        const int b1_k = 768 + s * 64;
#pragma unroll
        for (int j = 0; j < 4; j++) {
            int ca = tid + j * 256;
            int r = ca >> 3, c = ca & 7;
            cp_async16(sb + 2 * OP_BYTES + r * RSB + c * 16,
                       gB + (size_t)r * KA + b1_k + c * 8);
        }
    }
    CP_COMMIT();
}

__global__ __launch_bounds__(256, 2) void k_gemm(const float* __restrict__ bias,
                                                 float* __restrict__ Y) {
    extern __shared__ char dyn[];
    const uint32_t sbase = smem_u32(dyn);
    const int tid = threadIdx.x;
    const int wid = tid >> 5;
    const int lane = tid & 31;
    const int wm = wid & 1;
    const int wn = wid >> 1;
    const int mBase = blockIdx.y * BM;
    const int nBase = blockIdx.x * BN;

    const __nv_bfloat16* gA = g_A + (size_t)mBase * KA;
    const __nv_bfloat16* gB = g_B + (size_t)nBase * KA;

    float acc[4][4][4];
#pragma unroll
    for (int i = 0; i < 4; i++)
#pragma unroll
        for (int j = 0; j < 4; j++)
#pragma unroll
            for (int q = 0; q < 4; q++) acc[i][j][q] = 0.0f;

    const uint32_t aOff = (uint32_t)(wm * 64 + (lane & 15)) * RSB + ((lane >> 4) << 4);
    const uint32_t bOff = (uint32_t)(wn * 32 + (lane & 7) + ((lane >> 4) << 3)) * RSB +
                          (((lane >> 3) & 1) << 4);

    load_stage(sbase, gA, gB, 0, tid);

    for (int t = 0; t < NIT; t++) {
        cp_wait<0>();
        __syncthreads();
        if (t + 1 < NIT)
            load_stage(sbase + ((t + 1) & 1) * STAGE, gA, gB, t + 1, tid);

        const uint32_t st = sbase + (t & 1) * STAGE;
        const uint32_t Ab = st + aOff;
        const uint32_t Bb = st + OP_BYTES + bOff;
        const bool super = (t < 12);
#pragma unroll
        for (int kk = 0; kk < 4; kk++) {
            uint32_t a[4][4];
            uint32_t b[2][4];
#pragma unroll
            for (int im = 0; im < 4; im++)
                ldmat_x4(a[im][0], a[im][1], a[im][2], a[im][3],
                         Ab + im * (16 * RSB) + kk * 32);
#pragma unroll
            for (int jp = 0; jp < 2; jp++)
                ldmat_x4(b[jp][0], b[jp][1], b[jp][2], b[jp][3],
                         Bb + jp * (16 * RSB) + kk * 32);
#pragma unroll
            for (int im = 0; im < 4; im++)
#pragma unroll
                for (int jp = 0; jp < 2; jp++) {
                    mma16816(acc[im][2 * jp + 0], a[im], b[jp][0], b[jp][1]);
                    mma16816(acc[im][2 * jp + 1], a[im], b[jp][2], b[jp][3]);
                }
            if (super) {
#pragma unroll
                for (int jp = 0; jp < 2; jp++)
                    ldmat_x4(b[jp][0], b[jp][1], b[jp][2], b[jp][3],
                             Bb + OP_BYTES + jp * (16 * RSB) + kk * 32);
#pragma unroll
                for (int im = 0; im < 4; im++)
#pragma unroll
                    for (int jp = 0; jp < 2; jp++) {
                        mma16816(acc[im][2 * jp + 0], a[im], b[jp][0], b[jp][1]);
                        mma16816(acc[im][2 * jp + 1], a[im], b[jp][2], b[jp][3]);
                    }
            }
        }
    }

    // Epilogue: fp32 + bias
    const int row0 = mBase + wm * 64 + (lane >> 2);
    const int col0 = nBase + wn * 32 + (lane & 3) * 2;
#pragma unroll
    for (int im = 0; im < 4; im++) {
        int r = row0 + im * 16;
#pragma unroll
        for (int jn = 0; jn < 4; jn++) {
            int c = col0 + jn * 8;
            float2 bv = *(const float2*)(bias + c);
            float2 o0, o1;
            o0.x = acc[im][jn][0] + bv.x;
            o0.y = acc[im][jn][1] + bv.y;
            o1.x = acc[im][jn][2] + bv.x;
            o1.y = acc[im][jn][3] + bv.y;
            *(float2*)(Y + (size_t)r * OUTF + c) = o0;
            *(float2*)(Y + (size_t)(r + 8) * OUTF + c) = o1;
        }
    }
}

// ---------------------------------------------------------------------------
extern "C" void kernel_launch(void* const* d_in, const int* in_sizes, int n_in,
                              void* d_out, int out_size) {
    const float* x     = (const float*)d_in[0];
    const float* theta = (const float*)d_in[1];
    const float* W0    = (const float*)d_in[2];
    const float* bias  = (const float*)d_in[3];
    const float* BB    = (const float*)d_in[4];
    const float* GG    = (const float*)d_in[5];
    const int*   Pi    = (const int*)d_in[6];   // int32 (JAX x64 disabled)
    float* y = (float*)d_out;
    const int ntheta = in_sizes[1];             // 2048 -> rows 0,1 only

    float* u = nullptr;
    cudaGetSymbolAddress((void**)&u, g_u);

    static cudaStream_t s2 = nullptr;
    static cudaEvent_t ev_fork = nullptr, ev_join = nullptr;
    static bool init_done = false;
    if (!init_done) {
        cudaFuncSetAttribute(k_gemm, cudaFuncAttributeMaxDynamicSharedMemorySize,
                             NSTAGE * STAGE);
        cudaStreamCreateWithFlags(&s2, cudaStreamNonBlocking);
        cudaEventCreateWithFlags(&ev_fork, cudaEventDisableTiming);
        cudaEventCreateWithFlags(&ev_join, cudaEventDisableTiming);
        init_done = true;
    }

    // Fork: split_x (independent of Fastfood chain) runs on side stream
    cudaEventRecord(ev_fork, 0);
    cudaStreamWaitEvent(s2, ev_fork, 0);
    k_split_x<<<(MTOT * INF / 8 + 255) / 256, 256, 0, s2>>>(x);
    cudaEventRecord(ev_join, s2);

    // Fastfood weight chain on the main stream (warp-level FWHT, few barriers)
    k_ab<<<1, 64>>>(theta, BB, ntheta);
    k_gather_rows<<<128, 256>>>(Pi, GG);
    k_fwht_colA<<<128, 256>>>(u);                 // block 0 also computes g_scale
    k_fwht_colB_buildB<<<128, 256>>>(u, W0);      // fused: writes g_B directly

    // Join: GEMM needs both g_A (side stream) and g_B (main stream)
    cudaStreamWaitEvent(0, ev_join, 0);
    dim3 grid(OUTF / BN, MTOT / BM);
    k_gemm<<<grid, 256, NSTAGE * STAGE>>>(bias, y);
}

// round 17
// speedup vs baseline: 1.5689x; 1.5689x over previous
#include <cuda_runtime.h>
#include <cuda_bf16.h>
#include <cstdint>

// ---------------------------------------------------------------------------
// GlobalIntrinsicLinear: y = x @ (W0 + Fastfood(theta))^T + b
// Pass-1 FWHT collapsed analytically; pass-2 = two register stride-32 passes,
// with the 2nd pass fused into the W split (writes g_B directly, g_u dies).
// GEMM: bf16 3-term split with A-fragment sharing (12 super tiles
// Xhi*(Whi,Wlo) + 12 normal tiles Xlo*Whi), 2-stage double buffer, 2 CTA/SM,
// uniform 128x128 grid. (Verbatim R12 revert — proven 238.7 us.)
// ---------------------------------------------------------------------------

#define LL   (1 << 20)
#define DD   (1024 * 768)
#define OUTF 1024
#define INF  768
#define MTOT 16384
#define KA   1536          // 2 * 768 storage K
#define NIT  24            // 12 super + 12 normal tiles

#define BM 128
#define BN 128
#define RSB 144            // smem row stride bytes (128B data + 16B pad)
#define OP_BYTES (128 * RSB)       // 18432 per operand tile
#define STAGE   (3 * OP_BYTES)     // A + B0 + B1 = 55296
#define NSTAGE  2

// Scratch (device globals; no cudaMalloc allowed)
__device__ float g_a[1024];
__device__ float g_b[1024];
__device__ float g_u[LL];
__device__ float g_part[1024];
__device__ float g_scale;
__device__ __align__(16) __nv_bfloat16 g_A[(size_t)MTOT * KA];   // 50.3 MB
__device__ __align__(16) __nv_bfloat16 g_B[(size_t)OUTF * KA];   // 3 MB

// ======================= PTX helpers =======================================
__device__ __forceinline__ uint32_t smem_u32(const void* p) {
    uint32_t a;
    asm("{ .reg .u64 t; cvta.to.shared.u64 t, %1; cvt.u32.u64 %0, t; }" : "=r"(a) : "l"(p));
    return a;
}

__device__ __forceinline__ void cp_async16(uint32_t dst, const void* src) {
    asm volatile("cp.async.cg.shared.global [%0], [%1], 16;" :: "r"(dst), "l"(src));
}
#define CP_COMMIT() asm volatile("cp.async.commit_group;" ::: "memory")
template <int N>
__device__ __forceinline__ void cp_wait() {
    asm volatile("cp.async.wait_group %0;" :: "n"(N) : "memory");
}

__device__ __forceinline__ void ldmat_x4(uint32_t& r0, uint32_t& r1, uint32_t& r2,
                                         uint32_t& r3, uint32_t addr) {
    asm volatile("ldmatrix.sync.aligned.m8n8.x4.shared.b16 {%0,%1,%2,%3}, [%4];"
                 : "=r"(r0), "=r"(r1), "=r"(r2), "=r"(r3) : "r"(addr));
}

__device__ __forceinline__ void mma16816(float* d, const uint32_t* a,
                                         uint32_t b0, uint32_t b1) {
    asm volatile(
        "mma.sync.aligned.m16n8k16.row.col.f32.bf16.bf16.f32 "
        "{%0,%1,%2,%3}, {%4,%5,%6,%7}, {%8,%9}, {%0,%1,%2,%3};"
        : "+f"(d[0]), "+f"(d[1]), "+f"(d[2]), "+f"(d[3])
        : "r"(a[0]), "r"(a[1]), "r"(a[2]), "r"(a[3]), "r"(b0), "r"(b1));
}

// ======================= Fastfood kernels ==================================
__device__ __forceinline__ void fwht1024_r4(float* s) {
#pragma unroll
    for (int h = 1; h < 1024; h <<= 2) {
        int p = threadIdx.x;
        int j = ((p & ~(h - 1)) << 2) | (p & (h - 1));
        float x0 = s[j], x1 = s[j + h], x2 = s[j + 2 * h], x3 = s[j + 3 * h];
        float a0 = x0 + x1, a1 = x0 - x1, a2 = x2 + x3, a3 = x2 - x3;
        s[j] = a0 + a2;
        s[j + h] = a1 + a3;
        s[j + 2 * h] = a0 - a2;
        s[j + 3 * h] = a1 - a3;
        __syncthreads();
    }
}

__global__ void k_ab(const float* __restrict__ theta, const float* __restrict__ BB,
                     int ntheta) {
    __shared__ float s[1024];
    const int gbase = blockIdx.x * 1024;
    for (int j = threadIdx.x; j < 1024; j += 256) {
        int gi = gbase + j;
        float t = (gi < ntheta) ? theta[gi] : 0.0f;
        s[j] = BB[gi] * t;
    }
    __syncthreads();
    fwht1024_r4(s);
    float* dst = (blockIdx.x == 0) ? g_a : g_b;
    for (int j = threadIdx.x; j < 1024; j += 256) dst[j] = s[j];
}

__global__ void k_gather_rows(const int* __restrict__ Pi, const float* __restrict__ GG) {
    __shared__ float sa[1024], sb[1024], sr[1024];
    __shared__ float red[256];
    const int base = blockIdx.x * 1024;
    for (int j = threadIdx.x; j < 1024; j += 256) {
        sa[j] = g_a[j];
        sb[j] = g_b[j];
    }
    __syncthreads();
    float gsum = 0.0f;
    for (int j = threadIdx.x; j < 1024; j += 256) {
        int idx = Pi[base + j] & (LL - 1);
        int c = idx & 1023;
        float v = sa[c] + (((idx >> 10) & 1) ? -sb[c] : sb[c]);
        float g = GG[base + j];
        gsum += g * g;
        sr[j] = v * g;
    }
    __syncthreads();
    fwht1024_r4(sr);
    for (int j = threadIdx.x; j < 1024; j += 256) g_u[base + j] = sr[j];
    red[threadIdx.x] = gsum;
    __syncthreads();
    for (int st = 128; st > 0; st >>= 1) {
        if (threadIdx.x < st) red[threadIdx.x] += red[threadIdx.x + st];
        __syncthreads();
    }
    if (threadIdx.x == 0) g_part[blockIdx.x] = red[0];
}

__device__ __forceinline__ void fwht32_reg(float* r) {
#pragma unroll
    for (int h = 1; h < 32; h <<= 1) {
#pragma unroll
        for (int i = 0; i < 32; i++) {
            if ((i & h) == 0) {
                float a = r[i], b = r[i | h];
                r[i] = a + b;
                r[i | h] = a - b;
            }
        }
    }
}

// Column FWHT pass over bits 10..14 (element stride 1024).
// Block 0 additionally folds the GG^2 reduction into g_scale.
__global__ void k_fwht_colA(float* __restrict__ v) {
    if (blockIdx.x == 0) {
        __shared__ float sm[256];
        float s = 0.0f;
        for (int i = threadIdx.x; i < 1024; i += 256) s += g_part[i];
        sm[threadIdx.x] = s;
        __syncthreads();
        for (int st = 128; st > 0; st >>= 1) {
            if (threadIdx.x < st) sm[threadIdx.x] += sm[threadIdx.x + st];
            __syncthreads();
        }
        if (threadIdx.x == 0) g_scale = 1.0f / sqrtf(sm[0] * (float)DD);
    }
    int low = (blockIdx.x & 3) * 256 + threadIdx.x;
    int hi = blockIdx.x >> 2;
    size_t base = (size_t)hi * 32768 + low;
    float r[32];
#pragma unroll
    for (int m = 0; m < 32; m++) r[m] = v[base + (size_t)m * 1024];
    fwht32_reg(r);
#pragma unroll
    for (int m = 0; m < 32; m++) v[base + (size_t)m * 1024] = r[m];
}

__device__ __forceinline__ uint32_t pack_bf16x2(float x, float y) {
    __nv_bfloat162 h(__float2bfloat16(x), __float2bfloat16(y));
    return *(uint32_t*)&h;
}

// Column FWHT pass over bits 15..19 (stride 32768) fused with weight build:
// i = base + m*32768; i < DD <=> m < 24; writes split-bf16 g_B directly.
__global__ void k_fwht_colB_buildB(const float* __restrict__ v,
                                   const float* __restrict__ W0) {
    int low = (blockIdx.x & 3) * 256 + threadIdx.x;
    int r2 = blockIdx.x >> 2;
    size_t base = (size_t)r2 * 1024 + low;
    float r[32];
#pragma unroll
    for (int m = 0; m < 32; m++) r[m] = v[base + (size_t)m * 32768];
    fwht32_reg(r);
    const float sc = g_scale;
#pragma unroll
    for (int m = 0; m < 24; m++) {
        size_t i = base + (size_t)m * 32768;
        int n = (int)(i / 768);
        int k = (int)(i - (size_t)n * 768);
        float w = W0[i] + r[m] * sc;
        __nv_bfloat16 hi = __float2bfloat16(w);
        __nv_bfloat16 lo = __float2bfloat16(w - __bfloat162float(hi));
        size_t bb = (size_t)n * KA + k;
        g_B[bb] = hi;
        g_B[bb + INF] = lo;
    }
}

// ======================= Operand prep ======================================
__device__ __forceinline__ void split8(const float4 v0, const float4 v1,
                                       uint4& hi, uint4& lo) {
    float h0 = __bfloat162float(__float2bfloat16(v0.x));
    float h1 = __bfloat162float(__float2bfloat16(v0.y));
    float h2 = __bfloat162float(__float2bfloat16(v0.z));
    float h3 = __bfloat162float(__float2bfloat16(v0.w));
    float h4 = __bfloat162float(__float2bfloat16(v1.x));
    float h5 = __bfloat162float(__float2bfloat16(v1.y));
    float h6 = __bfloat162float(__float2bfloat16(v1.z));
    float h7 = __bfloat162float(__float2bfloat16(v1.w));
    hi.x = pack_bf16x2(v0.x, v0.y);
    hi.y = pack_bf16x2(v0.z, v0.w);
    hi.z = pack_bf16x2(v1.x, v1.y);
    hi.w = pack_bf16x2(v1.z, v1.w);
    lo.x = pack_bf16x2(v0.x - h0, v0.y - h1);
    lo.y = pack_bf16x2(v0.z - h2, v0.w - h3);
    lo.z = pack_bf16x2(v1.x - h4, v1.y - h5);
    lo.w = pack_bf16x2(v1.z - h6, v1.w - h7);
}

// A' = [Xhi | Xlo]
__global__ void k_split_x(const float* __restrict__ X) {
    int i8 = blockIdx.x * blockDim.x + threadIdx.x;
    if (i8 < MTOT * INF / 8) {
        int m = i8 / (INF / 8);
        int k = (i8 - m * (INF / 8)) * 8;
        const float* xp = X + (size_t)m * INF + k;
        float4 v0 = *(const float4*)(xp);
        float4 v1 = *(const float4*)(xp + 4);
        uint4 hi, lo;
        split8(v0, v1, hi, lo);
        size_t base = (size_t)m * KA + k;
        *(uint4*)(g_A + base) = hi;
        *(uint4*)(g_A + base + INF) = lo;
    }
}

// ======================= mma.sync GEMM =====================================
__device__ __forceinline__ void load_stage(uint32_t sb, const __nv_bfloat16* gA,
                                           const __nv_bfloat16* gB, int t, int tid) {
    const int s = (t < 12) ? t : t - 12;
    const int a_k = (t < 12) ? s * 64 : 768 + s * 64;
    const int b0_k = s * 64;
#pragma unroll
    for (int j = 0; j < 4; j++) {
        int ca = tid + j * 256;
        int r = ca >> 3, c = ca & 7;
        cp_async16(sb + r * RSB + c * 16, gA + (size_t)r * KA + a_k + c * 8);
    }
#pragma unroll
    for (int j = 0; j < 4; j++) {
        int ca = tid + j * 256;
        int r = ca >> 3, c = ca & 7;
        cp_async16(sb + OP_BYTES + r * RSB + c * 16, gB + (size_t)r * KA + b0_k + c * 8);
    }
    if (t < 12) {
        const int b1_k = 768 + s * 64;
#pragma unroll
        for (int j = 0; j < 4; j++) {
            int ca = tid + j * 256;
            int r = ca >> 3, c = ca & 7;
            cp_async16(sb + 2 * OP_BYTES + r * RSB + c * 16,
                       gB + (size_t)r * KA + b1_k + c * 8);
        }
    }
    CP_COMMIT();
}

__global__ __launch_bounds__(256, 2) void k_gemm(const float* __restrict__ bias,
                                                 float* __restrict__ Y) {
    extern __shared__ char dyn[];
    const uint32_t sbase = smem_u32(dyn);
    const int tid = threadIdx.x;
    const int wid = tid >> 5;
    const int lane = tid & 31;
    const int wm = wid & 1;
    const int wn = wid >> 1;
    const int mBase = blockIdx.y * BM;
    const int nBase = blockIdx.x * BN;

    const __nv_bfloat16* gA = g_A + (size_t)mBase * KA;
    const __nv_bfloat16* gB = g_B + (size_t)nBase * KA;

    float acc[4][4][4];
#pragma unroll
    for (int i = 0; i < 4; i++)
#pragma unroll
        for (int j = 0; j < 4; j++)
#pragma unroll
            for (int q = 0; q < 4; q++) acc[i][j][q] = 0.0f;

    const uint32_t aOff = (uint32_t)(wm * 64 + (lane & 15)) * RSB + ((lane >> 4) << 4);
    const uint32_t bOff = (uint32_t)(wn * 32 + (lane & 7) + ((lane >> 4) << 3)) * RSB +
                          (((lane >> 3) & 1) << 4);

    load_stage(sbase, gA, gB, 0, tid);

    for (int t = 0; t < NIT; t++) {
        cp_wait<0>();
        __syncthreads();
        if (t + 1 < NIT)
            load_stage(sbase + ((t + 1) & 1) * STAGE, gA, gB, t + 1, tid);

        const uint32_t st = sbase + (t & 1) * STAGE;
        const uint32_t Ab = st + aOff;
        const uint32_t Bb = st + OP_BYTES + bOff;
        const bool super = (t < 12);
#pragma unroll
        for (int kk = 0; kk < 4; kk++) {
            uint32_t a[4][4];
            uint32_t b[2][4];
#pragma unroll
            for (int im = 0; im < 4; im++)
                ldmat_x4(a[im][0], a[im][1], a[im][2], a[im][3],
                         Ab + im * (16 * RSB) + kk * 32);
#pragma unroll
            for (int jp = 0; jp < 2; jp++)
                ldmat_x4(b[jp][0], b[jp][1], b[jp][2], b[jp][3],
                         Bb + jp * (16 * RSB) + kk * 32);
#pragma unroll
            for (int im = 0; im < 4; im++)
#pragma unroll
                for (int jp = 0; jp < 2; jp++) {
                    mma16816(acc[im][2 * jp + 0], a[im], b[jp][0], b[jp][1]);
                    mma16816(acc[im][2 * jp + 1], a[im], b[jp][2], b[jp][3]);
                }
            if (super) {
#pragma unroll
                for (int jp = 0; jp < 2; jp++)
                    ldmat_x4(b[jp][0], b[jp][1], b[jp][2], b[jp][3],
                             Bb + OP_BYTES + jp * (16 * RSB) + kk * 32);
#pragma unroll
                for (int im = 0; im < 4; im++)
#pragma unroll
                    for (int jp = 0; jp < 2; jp++) {
                        mma16816(acc[im][2 * jp + 0], a[im], b[jp][0], b[jp][1]);
                        mma16816(acc[im][2 * jp + 1], a[im], b[jp][2], b[jp][3]);
                    }
            }
        }
    }

    // Epilogue: fp32 + bias
    const int row0 = mBase + wm * 64 + (lane >> 2);
    const int col0 = nBase + wn * 32 + (lane & 3) * 2;
#pragma unroll
    for (int im = 0; im < 4; im++) {
        int r = row0 + im * 16;
#pragma unroll
        for (int jn = 0; jn < 4; jn++) {
            int c = col0 + jn * 8;
            float2 bv = *(const float2*)(bias + c);
            float2 o0, o1;
            o0.x = acc[im][jn][0] + bv.x;
            o0.y = acc[im][jn][1] + bv.y;
            o1.x = acc[im][jn][2] + bv.x;
            o1.y = acc[im][jn][3] + bv.y;
            *(float2*)(Y + (size_t)r * OUTF + c) = o0;
            *(float2*)(Y + (size_t)(r + 8) * OUTF + c) = o1;
        }
    }
}

// ---------------------------------------------------------------------------
extern "C" void kernel_launch(void* const* d_in, const int* in_sizes, int n_in,
                              void* d_out, int out_size) {
    const float* x     = (const float*)d_in[0];
    const float* theta = (const float*)d_in[1];
    const float* W0    = (const float*)d_in[2];
    const float* bias  = (const float*)d_in[3];
    const float* BB    = (const float*)d_in[4];
    const float* GG    = (const float*)d_in[5];
    const int*   Pi    = (const int*)d_in[6];   // int32 (JAX x64 disabled)
    float* y = (float*)d_out;
    const int ntheta = in_sizes[1];             // 2048 -> rows 0,1 only

    float* u = nullptr;
    cudaGetSymbolAddress((void**)&u, g_u);

    static cudaStream_t s2 = nullptr;
    static cudaEvent_t ev_fork = nullptr, ev_join = nullptr;
    static bool init_done = false;
    if (!init_done) {
        cudaFuncSetAttribute(k_gemm, cudaFuncAttributeMaxDynamicSharedMemorySize,
                             NSTAGE * STAGE);
        cudaStreamCreateWithFlags(&s2, cudaStreamNonBlocking);
        cudaEventCreateWithFlags(&ev_fork, cudaEventDisableTiming);
        cudaEventCreateWithFlags(&ev_join, cudaEventDisableTiming);
        init_done = true;
    }

    // Fork: split_x (independent of Fastfood chain) runs on side stream
    cudaEventRecord(ev_fork, 0);
    cudaStreamWaitEvent(s2, ev_fork, 0);
    k_split_x<<<(MTOT * INF / 8 + 255) / 256, 256, 0, s2>>>(x);
    cudaEventRecord(ev_join, s2);

    // Fastfood weight chain on the main stream
    k_ab<<<2, 256>>>(theta, BB, ntheta);
    k_gather_rows<<<1024, 256>>>(Pi, GG);
    k_fwht_colA<<<128, 256>>>(u);                 // block 0 also computes g_scale
    k_fwht_colB_buildB<<<128, 256>>>(u, W0);      // fused: writes g_B directly

    // Join: GEMM needs both g_A (side stream) and g_B (main stream)
    cudaStreamWaitEvent(0, ev_join, 0);
    dim3 grid(OUTF / BN, MTOT / BM);
    k_gemm<<<grid, 256, NSTAGE * STAGE>>>(bias, y);
}